// round 17
// baseline (speedup 1.0000x reference)
#include <cuda_runtime.h>
#include <cuda_fp16.h>
#include <cstdint>
#include <math.h>

#define MAXN 100000
#define MAXE 1600000
#define PAD 64
#define LOG2E 1.44269504088896f

typedef unsigned long long ull;

// ---------------- scratch (static device globals; no allocs) ----------------
__device__ float  d_bufA[MAXN * 64];     // agg output (both layers)
__device__ float  d_bufB[MAXN * 64];     // h1
__device__ float  d_bufC[MAXN * 64];     // relu(LN(h1))
__device__ float  d_bufE[MAXN * 64];     // h0
__device__ uint4  d_P[MAXN * 16];        // per-node (vw,w) half2 pairs
__device__ int    d_cnt[MAXN];
__device__ int    d_adj[MAXN * PAD];
// fp16 transposed weights [j][k]
__device__ __half d_W1aT[8192], d_W1bT[8192], d_W2aT[8192], d_W2bT[8192];

// ---------------- mma.sync m16n8k16 + ldmatrix helpers ----------------------
__device__ __forceinline__ void mma16816(float& c0, float& c1, float& c2, float& c3,
                                         uint32_t a0, uint32_t a1, uint32_t a2,
                                         uint32_t a3, uint32_t b0, uint32_t b1) {
    asm volatile("mma.sync.aligned.m16n8k16.row.col.f32.f16.f16.f32 "
                 "{%0,%1,%2,%3}, {%4,%5,%6,%7}, {%8,%9}, {%0,%1,%2,%3};"
                 : "+f"(c0), "+f"(c1), "+f"(c2), "+f"(c3)
                 : "r"(a0), "r"(a1), "r"(a2), "r"(a3), "r"(b0), "r"(b1));
}
__device__ __forceinline__ void ldsm4(uint32_t& r0, uint32_t& r1, uint32_t& r2,
                                      uint32_t& r3, uint32_t saddr) {
    asm volatile("ldmatrix.sync.aligned.m8n8.x4.shared.b16 {%0,%1,%2,%3}, [%4];"
                 : "=r"(r0), "=r"(r1), "=r"(r2), "=r"(r3) : "r"(saddr));
}
__device__ __forceinline__ uint32_t s2u(const void* p) {
    uint32_t a;
    asm("{ .reg .u64 t; cvta.to.shared.u64 t, %1; cvt.u32.u64 %0, t; }" : "=r"(a) : "l"(p));
    return a;
}

// ---------------- encoder: h0 + P(t1) + zero cnt + fp16 weight transpose ----
__global__ void k_encoder(const float* __restrict__ x, const float* __restrict__ W,
                          const float* __restrict__ b, float* __restrict__ h,
                          uint4* __restrict__ P, const float* __restrict__ tptr,
                          int* __restrict__ cnt, int N,
                          const float* __restrict__ Wa1, const float* __restrict__ Wb1,
                          const float* __restrict__ Wa2, const float* __restrict__ Wb2,
                          __half* __restrict__ T1a, __half* __restrict__ T1b,
                          __half* __restrict__ T2a, __half* __restrict__ T2b) {
    __shared__ float4 sW[16 * 16];
    __shared__ float4 sB[16];
    int tid = threadIdx.x;
    if (tid < 256) sW[tid] = ((const float4*)W)[tid];
    if (tid < 16)  sB[tid] = ((const float4*)b)[tid];
    __syncthreads();
    int idx = blockIdx.x * blockDim.x + threadIdx.x;
    if (idx < N) cnt[idx] = 0;

    if (idx < 8192) {            // GEMM1 weights [64 k][128 j] -> T[j][k]
        int j = idx >> 6, k = idx & 63;
        T1a[j * 64 + k] = __float2half_rn(Wa1[k * 128 + j]);
        T2a[j * 64 + k] = __float2half_rn(Wa2[k * 128 + j]);
    } else if (idx < 16384) {    // GEMM2 weights [128 k][64 j] -> T[j][k]
        int i = idx - 8192;
        int j = i >> 7, k = i & 127;
        T1b[j * 128 + k] = __float2half_rn(Wb1[k * 64 + j]);
        T2b[j * 128 + k] = __float2half_rn(Wb2[k * 64 + j]);
    }

    int total = N * 16;
    if (idx >= total) return;
    int n = idx >> 4, q = idx & 15;
    const float4* xr = (const float4*)(x + n * 16);
    float4 x0 = xr[0], x1 = xr[1], x2 = xr[2], x3 = xr[3];
    float4 acc = sB[q];
    #define ESTEP(xv, kk) { float4 w = sW[(kk) * 16 + q]; \
        acc.x += (xv) * w.x; acc.y += (xv) * w.y; acc.z += (xv) * w.z; acc.w += (xv) * w.w; }
    ESTEP(x0.x, 0)  ESTEP(x0.y, 1)  ESTEP(x0.z, 2)  ESTEP(x0.w, 3)
    ESTEP(x1.x, 4)  ESTEP(x1.y, 5)  ESTEP(x1.z, 6)  ESTEP(x1.w, 7)
    ESTEP(x2.x, 8)  ESTEP(x2.y, 9)  ESTEP(x2.z, 10) ESTEP(x2.w, 11)
    ESTEP(x3.x, 12) ESTEP(x3.y, 13) ESTEP(x3.z, 14) ESTEP(x3.w, 15)
    #undef ESTEP
    ((float4*)h)[idx] = acc;
    float c = __ldg(tptr) * LOG2E;
    float vx = fmaxf(acc.x, 0.f) + 1e-7f;
    float vy = fmaxf(acc.y, 0.f) + 1e-7f;
    float vz = fmaxf(acc.z, 0.f) + 1e-7f;
    float vw = fmaxf(acc.w, 0.f) + 1e-7f;
    float wx = exp2f(vx * c), wy = exp2f(vy * c);
    float wz = exp2f(vz * c), ww = exp2f(vw * c);
    __half2 p0 = __floats2half2_rn(vx * wx, wx);
    __half2 p1 = __floats2half2_rn(vy * wy, wy);
    __half2 p2 = __floats2half2_rn(vz * wz, wz);
    __half2 p3 = __floats2half2_rn(vw * ww, ww);
    uint4 u;
    u.x = *(unsigned*)&p0; u.y = *(unsigned*)&p1;
    u.z = *(unsigned*)&p2; u.w = *(unsigned*)&p3;
    P[idx] = u;
}

// ---------------- bucket placement ----------------
__global__ void k_place(const int* __restrict__ src, const int* __restrict__ dst,
                        int* __restrict__ cnt, int* __restrict__ adj, int E) {
    int e = blockIdx.x * blockDim.x + threadIdx.x;
    if (e >= E) return;
    int d = dst[e];
    int p = atomicAdd(&cnt[d], 1);
    if (p < PAD) adj[(d << 6) + p] = src[e];
}

// ---------------- aggregation: fp16 P gather (round-6 best) ----------------
#define ACCP(p) { \
    float2 q0 = __half22float2(*(__half2*)&(p).x); \
    float2 q1 = __half22float2(*(__half2*)&(p).y); \
    float2 q2 = __half22float2(*(__half2*)&(p).z); \
    float2 q3 = __half22float2(*(__half2*)&(p).w); \
    n0 += q0.x; d0 += q0.y; n1 += q1.x; d1 += q1.y; \
    n2 += q2.x; d2 += q2.y; n3 += q3.x; d3 += q3.y; }

__global__ void __launch_bounds__(256)
k_agg(const float4* __restrict__ feat4, float4* __restrict__ out4,
      const uint4* __restrict__ P, const int* __restrict__ cnt,
      const int* __restrict__ adj, int N) {
    int gid = (blockIdx.x * 256 + threadIdx.x) >> 4;
    if (gid >= N) return;
    int f = threadIdx.x & 15;
    int deg = cnt[gid]; deg = min(deg, PAD);
    const int4* lst4 = (const int4*)(adj + (gid << 6));
    float n0 = 0.f, n1 = 0.f, n2 = 0.f, n3 = 0.f;
    float d0 = 0.f, d1 = 0.f, d2 = 0.f, d3 = 0.f;
    int full = deg >> 2;
    for (int c = 0; c < full; c++) {
        int4 s = lst4[c];
        uint4 p0 = P[s.x * 16 + f];
        uint4 p1 = P[s.y * 16 + f];
        uint4 p2 = P[s.z * 16 + f];
        uint4 p3 = P[s.w * 16 + f];
        ACCP(p0); ACCP(p1); ACCP(p2); ACCP(p3);
    }
    int r = deg & 3;
    if (r) {
        int4 s = lst4[full];
        uint4 p0 = P[s.x * 16 + f]; ACCP(p0);
        if (r > 1) { uint4 p1 = P[s.y * 16 + f]; ACCP(p1); }
        if (r > 2) { uint4 p2 = P[s.z * 16 + f]; ACCP(p2); }
    }
    float4 self = feat4[gid * 16 + f];
    float4 o;
    o.x = n0 / (d0 + 1e-16f) + self.x;
    o.y = n1 / (d1 + 1e-16f) + self.y;
    o.z = n2 / (d2 + 1e-16f) + self.z;
    o.w = n3 / (d3 + 1e-16f) + self.w;
    out4[gid * 16 + f] = o;
}

// ---------------- fused HMMA MLP (ldmatrix operand loads) -------------------
// smem halves: sW2 @0 [64][136]=8704 | sIN @8704 [128][72]=9216 | sW1 @17920 [128][72]
// hid overwrites sIN/sW1 region: @8704 [128][136]
#define M_W2H  0
#define M_INH  8704
#define M_W1H  17920
#define M_HIDH 8704
#define M_PARB 54272
#define M_TOT  (M_PARB + 640 * 4)

template <int MODE>
__global__ void __launch_bounds__(256)
k_mlp(const float* __restrict__ in, float* __restrict__ out,
      float* __restrict__ out2, const float* __restrict__ res,
      const __half* __restrict__ W1T, const float* __restrict__ b1,
      const float* __restrict__ g1, const float* __restrict__ be1,
      const __half* __restrict__ W2T, const float* __restrict__ b2,
      const float* __restrict__ gx, const float* __restrict__ bx,
      const float* __restrict__ Wl, const float* __restrict__ bl,
      uint4* __restrict__ Pout, const float* __restrict__ tp, int N) {
    extern __shared__ char smc[];
    __half* smh = (__half*)smc;
    float* pb1 = (float*)(smc + M_PARB);
    float* pg1 = pb1 + 128;
    float* pe1 = pg1 + 128;
    float* pb2 = pe1 + 128;
    float* pgx = pb2 + 64;
    float* pbx = pgx + 64;
    float* pwl = pbx + 64;
    const int tid = threadIdx.x;

    // ---- phase 1 loads ----
    {
        int row = tid >> 1, seg = tid & 1;
        int n = blockIdx.x * 128 + row;
        int nc = (n < N) ? n : (N - 1);
        const float4* ip = (const float4*)(in + (size_t)nc * 64);
        #pragma unroll
        for (int i = 0; i < 8; i++) {
            float4 v = ip[seg * 8 + i];
            __half2 ha = __floats2half2_rn(v.x, v.y);
            __half2 hb = __floats2half2_rn(v.z, v.w);
            uint2 u;
            u.x = *(unsigned*)&ha; u.y = *(unsigned*)&hb;
            *(uint2*)(smh + M_INH + row * 72 + seg * 32 + i * 4) = u;
        }
        const uint4* w1g = (const uint4*)W1T;       // [128][64] halves
        #pragma unroll
        for (int i = 0; i < 4; i++)
            *(uint4*)(smh + M_W1H + row * 72 + seg * 32 + i * 8) =
                w1g[row * 8 + seg * 4 + i];
        int r3 = tid >> 2, s3 = tid & 3;            // W2T [64][128]
        const uint4* w2g = (const uint4*)W2T;
        #pragma unroll
        for (int i = 0; i < 4; i++)
            *(uint4*)(smh + M_W2H + r3 * 136 + s3 * 32 + i * 8) =
                w2g[r3 * 16 + s3 * 4 + i];
        if (tid < 128) { pb1[tid] = b1[tid]; pg1[tid] = g1[tid]; pe1[tid] = be1[tid]; }
        else {
            int t2 = tid - 128;
            if (t2 < 64) {
                pb2[t2] = b2[t2]; pgx[t2] = gx[t2]; pbx[t2] = bx[t2];
                pwl[t2] = (MODE == 1) ? Wl[t2] : 0.f;
            }
        }
    }
    __syncthreads();

    const int lane = tid & 31, w = tid >> 5;
    const int gid = lane >> 2, tig = lane & 3;
    const int m0 = w * 16;
    const uint32_t sb = s2u(smh);

    // ldmatrix lane-address components
    const int lr   = lane & 15;                    // A row within 16
    const int lc8  = (lane >> 4) << 3;             // A col half: 0/8
    const int brow = ((lane >> 4) << 3) | (lane & 7);  // B row pattern 0..15
    const int bcol = ((lane >> 3) & 1) << 3;       // B col half pattern

    // ---- GEMM1: [128 x 128 x 64] ----
    float acc[64];
    #pragma unroll
    for (int i = 0; i < 64; i++) acc[i] = 0.f;
    {
        const uint32_t aadr = sb + (uint32_t)(M_INH + (m0 + lr) * 72 + lc8) * 2;
        const uint32_t badr = sb + (uint32_t)(M_W1H + brow * 72 + bcol) * 2;
        #pragma unroll
        for (int ks = 0; ks < 4; ks++) {
            uint32_t a0, a1, a2, a3;
            ldsm4(a0, a1, a2, a3, aadr + ks * 32);
            #pragma unroll
            for (int ntp = 0; ntp < 8; ntp++) {
                uint32_t r0, r1, r2, r3;
                ldsm4(r0, r1, r2, r3, badr + (uint32_t)(ntp * 16 * 72) * 2 + ks * 32);
                int n0i = ntp * 2;
                mma16816(acc[n0i*4+0], acc[n0i*4+1], acc[n0i*4+2], acc[n0i*4+3],
                         a0, a1, a2, a3, r0, r1);
                mma16816(acc[n0i*4+4], acc[n0i*4+5], acc[n0i*4+6], acc[n0i*4+7],
                         a0, a1, a2, a3, r2, r3);
            }
        }
    }

    // ---- bias + LN128 stats ----
    float s0 = 0.f, q0 = 0.f, s1 = 0.f, q1 = 0.f;
    #pragma unroll
    for (int nt = 0; nt < 16; nt++) {
        int j0 = nt * 8 + tig * 2;
        float2 bb = *(float2*)&pb1[j0];
        float v0 = acc[nt*4+0] + bb.x, v1 = acc[nt*4+1] + bb.y;
        float v2 = acc[nt*4+2] + bb.x, v3 = acc[nt*4+3] + bb.y;
        acc[nt*4+0] = v0; acc[nt*4+1] = v1; acc[nt*4+2] = v2; acc[nt*4+3] = v3;
        s0 += v0 + v1; q0 += v0*v0 + v1*v1;
        s1 += v2 + v3; q1 += v2*v2 + v3*v3;
    }
    s0 += __shfl_xor_sync(0xffffffffu, s0, 1); s0 += __shfl_xor_sync(0xffffffffu, s0, 2);
    q0 += __shfl_xor_sync(0xffffffffu, q0, 1); q0 += __shfl_xor_sync(0xffffffffu, q0, 2);
    s1 += __shfl_xor_sync(0xffffffffu, s1, 1); s1 += __shfl_xor_sync(0xffffffffu, s1, 2);
    q1 += __shfl_xor_sync(0xffffffffu, q1, 1); q1 += __shfl_xor_sync(0xffffffffu, q1, 2);
    float mu0 = s0 * (1.f / 128.f), iv0 = rsqrtf(q0 * (1.f / 128.f) - mu0 * mu0 + 1e-5f);
    float mu1 = s1 * (1.f / 128.f), iv1 = rsqrtf(q1 * (1.f / 128.f) - mu1 * mu1 + 1e-5f);

    // wait for ALL warps to finish reading sIN/sW1 before overwriting with hid
    __syncthreads();

    // ---- LN + ReLU -> fp16 hid [128][136] (own rows only) ----
    #pragma unroll
    for (int nt = 0; nt < 16; nt++) {
        int j0 = nt * 8 + tig * 2;
        float2 gg = *(float2*)&pg1[j0];
        float2 ee = *(float2*)&pe1[j0];
        float y00 = fmaxf((acc[nt*4+0] - mu0) * iv0 * gg.x + ee.x, 0.f);
        float y01 = fmaxf((acc[nt*4+1] - mu0) * iv0 * gg.y + ee.y, 0.f);
        float y10 = fmaxf((acc[nt*4+2] - mu1) * iv1 * gg.x + ee.x, 0.f);
        float y11 = fmaxf((acc[nt*4+3] - mu1) * iv1 * gg.y + ee.y, 0.f);
        __half2 h0 = __floats2half2_rn(y00, y01);
        __half2 h1v = __floats2half2_rn(y10, y11);
        *(uint32_t*)(smh + M_HIDH + (m0 + gid) * 136 + j0)     = *(unsigned*)&h0;
        *(uint32_t*)(smh + M_HIDH + (m0 + gid + 8) * 136 + j0) = *(unsigned*)&h1v;
    }
    __syncwarp();

    // ---- GEMM2: [128 x 64 x 128] (A = own hid rows; no block sync needed) --
    float acc2[32];
    #pragma unroll
    for (int i = 0; i < 32; i++) acc2[i] = 0.f;
    {
        const uint32_t aadr = sb + (uint32_t)(M_HIDH + (m0 + lr) * 136 + lc8) * 2;
        const uint32_t badr = sb + (uint32_t)(M_W2H + brow * 136 + bcol) * 2;
        #pragma unroll
        for (int ks = 0; ks < 8; ks++) {
            uint32_t a0, a1, a2, a3;
            ldsm4(a0, a1, a2, a3, aadr + ks * 32);
            #pragma unroll
            for (int ntp = 0; ntp < 4; ntp++) {
                uint32_t r0, r1, r2, r3;
                ldsm4(r0, r1, r2, r3, badr + (uint32_t)(ntp * 16 * 136) * 2 + ks * 32);
                int n0i = ntp * 2;
                mma16816(acc2[n0i*4+0], acc2[n0i*4+1], acc2[n0i*4+2], acc2[n0i*4+3],
                         a0, a1, a2, a3, r0, r1);
                mma16816(acc2[n0i*4+4], acc2[n0i*4+5], acc2[n0i*4+6], acc2[n0i*4+7],
                         a0, a1, a2, a3, r2, r3);
            }
        }
    }

    const int node0 = blockIdx.x * 128 + m0 + gid;
    const int node1 = node0 + 8;
    const int nc0 = (node0 < N) ? node0 : (N - 1);
    const int nc1 = (node1 < N) ? node1 : (N - 1);

    // ---- bias (+res), h1 store (MODE 0), LN64 stats ----
    float sa = 0.f, qa = 0.f, sb2 = 0.f, qb = 0.f;
    #pragma unroll
    for (int nt = 0; nt < 8; nt++) {
        int j0 = nt * 8 + tig * 2;
        float2 bb = *(float2*)&pb2[j0];
        float v0 = acc2[nt*4+0] + bb.x, v1 = acc2[nt*4+1] + bb.y;
        float v2 = acc2[nt*4+2] + bb.x, v3 = acc2[nt*4+3] + bb.y;
        if (MODE == 1) {
            float2 r0 = *(const float2*)(res + (size_t)nc0 * 64 + j0);
            float2 r1 = *(const float2*)(res + (size_t)nc1 * 64 + j0);
            v0 += r0.x; v1 += r0.y; v2 += r1.x; v3 += r1.y;
        } else {
            if (node0 < N) *(float2*)(out + (size_t)node0 * 64 + j0) = make_float2(v0, v1);
            if (node1 < N) *(float2*)(out + (size_t)node1 * 64 + j0) = make_float2(v2, v3);
        }
        acc2[nt*4+0] = v0; acc2[nt*4+1] = v1; acc2[nt*4+2] = v2; acc2[nt*4+3] = v3;
        sa += v0 + v1; qa += v0*v0 + v1*v1;
        sb2 += v2 + v3; qb += v2*v2 + v3*v3;
    }
    sa += __shfl_xor_sync(0xffffffffu, sa, 1); sa += __shfl_xor_sync(0xffffffffu, sa, 2);
    qa += __shfl_xor_sync(0xffffffffu, qa, 1); qa += __shfl_xor_sync(0xffffffffu, qa, 2);
    sb2 += __shfl_xor_sync(0xffffffffu, sb2, 1); sb2 += __shfl_xor_sync(0xffffffffu, sb2, 2);
    qb += __shfl_xor_sync(0xffffffffu, qb, 1); qb += __shfl_xor_sync(0xffffffffu, qb, 2);
    float mu0b = sa * (1.f / 64.f), iv0b = rsqrtf(qa * (1.f / 64.f) - mu0b * mu0b + 1e-5f);
    float mu1b = sb2 * (1.f / 64.f), iv1b = rsqrtf(qb * (1.f / 64.f) - mu1b * mu1b + 1e-5f);

    if (MODE == 0) {
        float cP = __ldg(tp) * LOG2E;
        unsigned* P32 = (unsigned*)Pout;
        #pragma unroll
        for (int nt = 0; nt < 8; nt++) {
            int j0 = nt * 8 + tig * 2;
            float2 gg = *(float2*)&pgx[j0];
            float2 ee = *(float2*)&pbx[j0];
            float y00 = fmaxf((acc2[nt*4+0] - mu0b) * iv0b * gg.x + ee.x, 0.f);
            float y01 = fmaxf((acc2[nt*4+1] - mu0b) * iv0b * gg.y + ee.y, 0.f);
            float y10 = fmaxf((acc2[nt*4+2] - mu1b) * iv1b * gg.x + ee.x, 0.f);
            float y11 = fmaxf((acc2[nt*4+3] - mu1b) * iv1b * gg.y + ee.y, 0.f);
            if (node0 < N) {
                *(float2*)(out2 + (size_t)node0 * 64 + j0) = make_float2(y00, y01);
                float va = y00 + 1e-7f, vb = y01 + 1e-7f;
                float wa = exp2f(va * cP), wb = exp2f(vb * cP);
                __half2 pa = __floats2half2_rn(va * wa, wa);
                __half2 pbh = __floats2half2_rn(vb * wb, wb);
                P32[(size_t)node0 * 64 + j0]     = *(unsigned*)&pa;
                P32[(size_t)node0 * 64 + j0 + 1] = *(unsigned*)&pbh;
            }
            if (node1 < N) {
                *(float2*)(out2 + (size_t)node1 * 64 + j0) = make_float2(y10, y11);
                float va = y10 + 1e-7f, vb = y11 + 1e-7f;
                float wa = exp2f(va * cP), wb = exp2f(vb * cP);
                __half2 pa = __floats2half2_rn(va * wa, wa);
                __half2 pbh = __floats2half2_rn(vb * wb, wb);
                P32[(size_t)node1 * 64 + j0]     = *(unsigned*)&pa;
                P32[(size_t)node1 * 64 + j0 + 1] = *(unsigned*)&pbh;
            }
        }
    } else {
        float dd0 = 0.f, dd1 = 0.f;
        #pragma unroll
        for (int nt = 0; nt < 8; nt++) {
            int j0 = nt * 8 + tig * 2;
            float2 gg = *(float2*)&pgx[j0];
            float2 ee = *(float2*)&pbx[j0];
            float2 wl = *(float2*)&pwl[j0];
            float y00 = fmaxf((acc2[nt*4+0] - mu0b) * iv0b * gg.x + ee.x, 0.f);
            float y01 = fmaxf((acc2[nt*4+1] - mu0b) * iv0b * gg.y + ee.y, 0.f);
            float y10 = fmaxf((acc2[nt*4+2] - mu1b) * iv1b * gg.x + ee.x, 0.f);
            float y11 = fmaxf((acc2[nt*4+3] - mu1b) * iv1b * gg.y + ee.y, 0.f);
            dd0 += y00 * wl.x + y01 * wl.y;
            dd1 += y10 * wl.x + y11 * wl.y;
        }
        dd0 += __shfl_xor_sync(0xffffffffu, dd0, 1); dd0 += __shfl_xor_sync(0xffffffffu, dd0, 2);
        dd1 += __shfl_xor_sync(0xffffffffu, dd1, 1); dd1 += __shfl_xor_sync(0xffffffffu, dd1, 2);
        if (tig == 0) {
            float blv = __ldg(bl);
            if (node0 < N) {
                float logit = dd0 + blv;
                out[node0]     = 1.f / (1.f + expf(-logit));
                out[N + node0] = logit;
            }
            if (node1 < N) {
                float logit = dd1 + blv;
                out[node1]     = 1.f / (1.f + expf(-logit));
                out[N + node1] = logit;
            }
        }
    }
}

// ---------------- host launcher ----------------
extern "C" void kernel_launch(void* const* d_in, const int* in_sizes, int n_in,
                              void* d_out, int out_size) {
    const float* x      = (const float*)d_in[0];
    const int*   eidx   = (const int*)d_in[1];
    const float* W_enc  = (const float*)d_in[2];
    const float* b_enc  = (const float*)d_in[3];
    const float* t1     = (const float*)d_in[4];
    const float* W1a    = (const float*)d_in[5];
    const float* b1a    = (const float*)d_in[6];
    const float* g1a    = (const float*)d_in[7];
    const float* be1a   = (const float*)d_in[8];
    const float* W1b    = (const float*)d_in[9];
    const float* b1b    = (const float*)d_in[10];
    const float* g_n1   = (const float*)d_in[11];
    const float* b_n1   = (const float*)d_in[12];
    const float* t2     = (const float*)d_in[13];
    const float* W2a    = (const float*)d_in[14];
    const float* b2a    = (const float*)d_in[15];
    const float* g2a    = (const float*)d_in[16];
    const float* be2a   = (const float*)d_in[17];
    const float* W2b    = (const float*)d_in[18];
    const float* b2b    = (const float*)d_in[19];
    const float* g_n0   = (const float*)d_in[20];
    const float* b_n0   = (const float*)d_in[21];
    const float* W_lin  = (const float*)d_in[22];
    const float* b_lin  = (const float*)d_in[23];
    float* out = (float*)d_out;

    int N = in_sizes[0] / 16;
    int E = in_sizes[1] / 2;
    if (N > MAXN) N = MAXN;
    if (E > MAXE) E = MAXE;
    const int* src = eidx;
    const int* dst = eidx + E;

    float *pA, *pB, *pC, *pE;
    uint4* pP;
    __half *T1a, *T1b, *T2a, *T2b;
    int *pCnt, *pAdj;
    cudaGetSymbolAddress((void**)&pA, d_bufA);
    cudaGetSymbolAddress((void**)&pB, d_bufB);
    cudaGetSymbolAddress((void**)&pC, d_bufC);
    cudaGetSymbolAddress((void**)&pE, d_bufE);
    cudaGetSymbolAddress((void**)&pP, d_P);
    cudaGetSymbolAddress((void**)&pCnt, d_cnt);
    cudaGetSymbolAddress((void**)&pAdj, d_adj);
    cudaGetSymbolAddress((void**)&T1a, d_W1aT);
    cudaGetSymbolAddress((void**)&T1b, d_W1bT);
    cudaGetSymbolAddress((void**)&T2a, d_W2aT);
    cudaGetSymbolAddress((void**)&T2b, d_W2bT);

    cudaFuncSetAttribute(k_mlp<0>, cudaFuncAttributeMaxDynamicSharedMemorySize, M_TOT);
    cudaFuncSetAttribute(k_mlp<1>, cudaFuncAttributeMaxDynamicSharedMemorySize, M_TOT);

    int mlp_grid = (N + 127) / 128;
    int agg_grid = (N * 16 + 255) / 256;

    // (1) encoder -> h0 + layer-1 P + zero cnt + fp16 weight transpose
    k_encoder<<<(N * 16 + 255) / 256, 256>>>(x, W_enc, b_enc, pE, pP, t1, pCnt, N,
                                             W1a, W1b, W2a, W2b,
                                             T1a, T1b, T2a, T2b);
    // (2) bucket placement
    k_place<<<(E + 255) / 256, 256>>>(src, dst, pCnt, pAdj, E);
    // (3) layer-1 aggregation
    k_agg<<<agg_grid, 256>>>((const float4*)pE, (float4*)pA, pP, pCnt, pAdj, N);
    // (4) fused MLP1 (HMMA + ldmatrix) -> h1, relu(LN(h1)), layer-2 P [profiled]
    k_mlp<0><<<mlp_grid, 256, M_TOT>>>(pA, pB, pC, (const float*)0,
                                       T1a, b1a, g1a, be1a,
                                       T1b, b1b, g_n1, b_n1,
                                       (const float*)0, (const float*)0, pP, t2, N);
    // (5) layer-2 aggregation
    k_agg<<<agg_grid, 256>>>((const float4*)pC, (float4*)pA, pP, pCnt, pAdj, N);
    // (6) fused MLP2 (HMMA + ldmatrix) + residual + final head -> out
    k_mlp<1><<<mlp_grid, 256, M_TOT>>>(pA, out, (float*)0, pB,
                                       T2a, b2a, g2a, be2a,
                                       T2b, b2b, g_n0, b_n0,
                                       W_lin, b_lin, (uint4*)0, (const float*)0, N);
}